// round 2
// baseline (speedup 1.0000x reference)
#include <cuda_runtime.h>

// Problem constants (fixed shapes from reference setup_inputs)
#define NPTS    2048
#define UPR     10
#define QTOT    (NPTS*UPR + NPTS)    // 22528 queries
#define KNN     5
#define THREADS 256
#define SPLIT   4                    // threads per query
#define QPB     (THREADS/SPLIT)      // 64 queries / block
#define NBLOCKS (QTOT/QPB)           // 352
#define EPS_D   1e-8f
#define EPS_N   1e-10f
#define BETA    3.0f
#define STDV    0.05f

__device__ float g_partial[NBLOCKS];

// Branchless insert of r into sorted-ascending s[0..4] (keep 5 smallest).
__device__ __forceinline__ void ins5v(float r, float s[KNN]) {
    s[4] = fminf(s[4], fmaxf(s[3], r));
    s[3] = fminf(s[3], fmaxf(s[2], r));
    s[2] = fminf(s[2], fmaxf(s[1], r));
    s[1] = fminf(s[1], fmaxf(s[0], r));
    s[0] = fminf(s[0], r);
}

// Merge partner's top-5 values into mine (within the 4-thread group).
__device__ __forceinline__ void merge5v(int xorMask, float s[KNN]) {
    float o[KNN];
#pragma unroll
    for (int k = 0; k < KNN; ++k)
        o[k] = __shfl_xor_sync(0xFFFFFFFFu, s[k], xorMask);
#pragma unroll
    for (int k = 0; k < KNN; ++k) ins5v(o[k], s);
}

__global__ __launch_bounds__(THREADS)
void dirdist_kernel(const float* __restrict__ src,
                    const float* __restrict__ tgt,
                    const float* __restrict__ noise)
{
    __shared__ float4 sT[NPTS];   // {x,y,z,|p|^2}  32 KB
    __shared__ float4 sS[NPTS];   //                32 KB

    const int tid = threadIdx.x;

    // Cooperative load + |p|^2 precompute.
    for (int i = tid; i < NPTS; i += THREADS) {
        float x = tgt[3*i], y = tgt[3*i+1], z = tgt[3*i+2];
        sT[i] = make_float4(x, y, z, fmaf(x, x, fmaf(y, y, z * z)));
        x = src[3*i]; y = src[3*i+1]; z = src[3*i+2];
        sS[i] = make_float4(x, y, z, fmaf(x, x, fmaf(y, y, z * z)));
    }
    __syncthreads();

    const int qi  = blockIdx.x * QPB + (tid >> 2);
    const int par = tid & 3;

    // Query point.
    float qx, qy, qz;
    if (qi < NPTS * UPR) {
        int m = qi / UPR;
        float4 t = sT[m];
        qx = fmaf(noise[3*qi + 0], STDV, t.x);
        qy = fmaf(noise[3*qi + 1], STDV, t.y);
        qz = fmaf(noise[3*qi + 2], STDV, t.z);
    } else {
        float4 s = sS[qi - NPTS * UPR];
        qx = s.x; qy = s.y; qz = s.z;
    }
    const float qx2 = -2.0f * qx, qy2 = -2.0f * qy, qz2 = -2.0f * qz;
    const float q2  = fmaf(qx, qx, fmaf(qy, qy, qz * qz));

    // ---------- Phase 1: branchless top-5 (values only) in r-space ----------
    float dT[KNN], dS[KNN];
#pragma unroll
    for (int k = 0; k < KNN; ++k) { dT[k] = 3.0e38f; dS[k] = 3.0e38f; }

#pragma unroll 4
    for (int jj = 0; jj < NPTS / SPLIT; ++jj) {
        int j = (jj << 2) + par;
        float4 pt = sT[j];
        float rt = fmaf(pt.x, qx2, fmaf(pt.y, qy2, fmaf(pt.z, qz2, pt.w)));
        ins5v(rt, dT);
        float4 ps = sS[j];
        float rs = fmaf(ps.x, qx2, fmaf(ps.y, qy2, fmaf(ps.z, qz2, ps.w)));
        ins5v(rs, dS);
    }

    // Merge across the 4-thread group -> union top-5 thresholds.
    merge5v(1, dT); merge5v(2, dT);
    merge5v(1, dS); merge5v(2, dS);
    const float rT5 = dT[4];
    const float rS5 = dS[4];

    // ---------- Phase 2: rescan, accumulate inv-sum and inv-weighted dir ----
    float aT = 0.f, gTx = 0.f, gTy = 0.f, gTz = 0.f;
    float aS = 0.f, gSx = 0.f, gSy = 0.f, gSz = 0.f;

#pragma unroll 4
    for (int jj = 0; jj < NPTS / SPLIT; ++jj) {
        int j = (jj << 2) + par;
        float4 pt = sT[j];
        float rt = fmaf(pt.x, qx2, fmaf(pt.y, qy2, fmaf(pt.z, qz2, pt.w)));
        if (rt <= rT5) {
            float d = fmaxf(rt + q2, 0.0f) + EPS_D;
            float w = 1.0f / d;
            aT += w;
            gTx = fmaf(qx - pt.x, w, gTx);
            gTy = fmaf(qy - pt.y, w, gTy);
            gTz = fmaf(qz - pt.z, w, gTz);
        }
        float4 ps = sS[j];
        float rs = fmaf(ps.x, qx2, fmaf(ps.y, qy2, fmaf(ps.z, qz2, ps.w)));
        if (rs <= rS5) {
            float d = fmaxf(rs + q2, 0.0f) + EPS_D;
            float w = 1.0f / d;
            aS += w;
            gSx = fmaf(qx - ps.x, w, gSx);
            gSy = fmaf(qy - ps.y, w, gSy);
            gSz = fmaf(qz - ps.z, w, gSz);
        }
    }

    // Butterfly-reduce the 8 accumulators within the 4-thread group.
#pragma unroll
    for (int m = 1; m <= 2; m <<= 1) {
        aT  += __shfl_xor_sync(0xFFFFFFFFu, aT,  m);
        gTx += __shfl_xor_sync(0xFFFFFFFFu, gTx, m);
        gTy += __shfl_xor_sync(0xFFFFFFFFu, gTy, m);
        gTz += __shfl_xor_sync(0xFFFFFFFFu, gTz, m);
        aS  += __shfl_xor_sync(0xFFFFFFFFu, aS,  m);
        gSx += __shfl_xor_sync(0xFFFFFFFFu, gSx, m);
        gSy += __shfl_xor_sync(0xFFFFFFFFu, gSy, m);
        gSz += __shfl_xor_sync(0xFFFFFFFFu, gSz, m);
    }

    float contrib = 0.f;
    if (par == 0) {
        float invT = 1.0f / aT, invS = 1.0f / aS;
        float tX = gTx * invT, tY = gTy * invT, tZ = gTz * invT;
        float sX = gSx * invS, sY = gSy * invS, sZ = gSz * invS;
        float axT = tX + EPS_N, ayT = tY + EPS_N, azT = tZ + EPS_N;
        float axS = sX + EPS_N, ayS = sY + EPS_N, azS = sZ + EPS_N;
        float uT = sqrtf(fmaf(axT, axT, fmaf(ayT, ayT, azT * azT)));
        float uS = sqrtf(fmaf(axS, axS, fmaf(ayS, ayS, azS * azS)));
        float e1 = fabsf(uT - uS);
        float e2 = fabsf(sX - tX) + fabsf(sY - tY) + fabsf(sZ - tZ);
        float t  = e1 + e2;
        contrib  = t * __expf(-BETA * t);
    }

    // Block reduction (smem reused after sync).
#pragma unroll
    for (int o = 16; o > 0; o >>= 1)
        contrib += __shfl_down_sync(0xFFFFFFFFu, contrib, o);

    __syncthreads();
    float* scratch = (float*)sT;
    if ((tid & 31) == 0) scratch[tid >> 5] = contrib;
    __syncthreads();
    if (tid == 0) {
        float s = 0.f;
#pragma unroll
        for (int w = 0; w < THREADS / 32; ++w) s += scratch[w];
        g_partial[blockIdx.x] = s;
    }
}

__global__ void dirdist_reduce(float* __restrict__ out)
{
    __shared__ float sh[8];
    int tid = threadIdx.x;
    float v = 0.f;
    for (int i = tid; i < NBLOCKS; i += 256) v += g_partial[i];
#pragma unroll
    for (int o = 16; o > 0; o >>= 1) v += __shfl_down_sync(0xFFFFFFFFu, v, o);
    if ((tid & 31) == 0) sh[tid >> 5] = v;
    __syncthreads();
    if (tid == 0) {
        float s = 0.f;
#pragma unroll
        for (int w = 0; w < 8; ++w) s += sh[w];
        out[0] = s * (1.0f / (float)QTOT);
    }
}

extern "C" void kernel_launch(void* const* d_in, const int* in_sizes, int n_in,
                              void* d_out, int out_size)
{
    const float* src   = (const float*)d_in[0];
    const float* tgt   = (const float*)d_in[1];
    const float* noise = (const float*)d_in[2];
    (void)in_sizes; (void)n_in; (void)out_size;

    dirdist_kernel<<<NBLOCKS, THREADS>>>(src, tgt, noise);
    dirdist_reduce<<<1, 256>>>((float*)d_out);
}

// round 3
// speedup vs baseline: 2.4828x; 2.4828x over previous
#include <cuda_runtime.h>

#define NPTS    2048
#define UPR     10
#define NJIT    (NPTS*UPR)           // 20480 jittered queries
#define QTOT    (NJIT + NPTS)        // 22528 total queries
#define KNN     5
#define T1      128                  // kernel1 block size
#define GX1     (QTOT/T1)            // 176
#define T2      256
#define NB2     (QTOT/T2)            // 88
#define EPS_D   1e-8f
#define EPS_N   1e-10f
#define BETA    3.0f
#define STDV    0.05f
#define IDXMASK 0xFFFFF800u          // keep 21 high bits of d2, 11 low bits = index

// Per-(cloud, query) weighted udf gradient. [0]=tgt cloud, [1]=src cloud.
__device__ float4 g_grad[2][QTOT];
__device__ float  g_partial[NB2];

__global__ __launch_bounds__(T1)
void knn_grad_kernel(const float* __restrict__ src,
                     const float* __restrict__ tgt,
                     const float* __restrict__ noise)
{
    __shared__ float4 sC[NPTS];      // {x, y, z, |p|^2}  32 KB

    const int tid   = threadIdx.x;
    const int cloud = blockIdx.y;    // 0 = tgt, 1 = src
    const float* __restrict__ pts = cloud ? src : tgt;

    // Cooperative load of this block's cloud.
    for (int i = tid; i < NPTS; i += T1) {
        float x = pts[3*i], y = pts[3*i+1], z = pts[3*i+2];
        sC[i] = make_float4(x, y, z, fmaf(x, x, fmaf(y, y, z * z)));
    }
    __syncthreads();

    // Build this lane's query point (global loads; L2-cached, once per thread).
    const int qi = blockIdx.x * T1 + tid;
    float qx, qy, qz;
    if (qi < NJIT) {
        int m = qi / UPR;
        qx = fmaf(noise[3*qi + 0], STDV, tgt[3*m + 0]);
        qy = fmaf(noise[3*qi + 1], STDV, tgt[3*m + 1]);
        qz = fmaf(noise[3*qi + 2], STDV, tgt[3*m + 2]);
    } else {
        int m = qi - NJIT;
        qx = src[3*m + 0];
        qy = src[3*m + 1];
        qz = src[3*m + 2];
    }
    const float qx2 = -2.0f * qx, qy2 = -2.0f * qy, qz2 = -2.0f * qz;
    const float q2  = fmaf(qx, qx, fmaf(qy, qy, qz * qz));

    // Top-5 packed keys (ascending). Init huge.
    int s0 = 0x7F000000, s1 = 0x7F000001, s2 = 0x7F000002,
        s3 = 0x7F000003, s4 = 0x7F000004;
    float thF = __int_as_float(s4);

#pragma unroll 4
    for (int j = 0; j < NPTS; ++j) {
        float4 p = sC[j];
        float r  = fmaf(p.x, qx2, fmaf(p.y, qy2, fmaf(p.z, qz2, p.w)));
        float d2 = r + q2;
        if (d2 < thF) {
            int key = (int)((__float_as_uint(fmaxf(d2, 0.0f)) & IDXMASK) | (unsigned)j);
            s4 = key;
            int a;
            a = min(s3, s4); s4 = max(s3, s4); s3 = a;
            a = min(s2, s3); s3 = max(s2, s3); s2 = a;
            a = min(s1, s2); s2 = max(s1, s2); s1 = a;
            a = min(s0, s1); s1 = max(s0, s1); s0 = a;
            thF = __int_as_float(s4);
        }
    }

    // Exact recompute for the 5 selected indices; accumulate weighted gradient.
    float aw = 0.f, gx = 0.f, gy = 0.f, gz = 0.f;
    int keys[KNN] = {s0, s1, s2, s3, s4};
#pragma unroll
    for (int k = 0; k < KNN; ++k) {
        int idx = keys[k] & 2047;
        float4 p = sC[idx];
        float r  = fmaf(p.x, qx2, fmaf(p.y, qy2, fmaf(p.z, qz2, p.w)));
        float d2 = fmaxf(r + q2, 0.0f);
        float w  = 1.0f / (d2 + EPS_D);
        aw += w;
        gx = fmaf(qx - p.x, w, gx);
        gy = fmaf(qy - p.y, w, gy);
        gz = fmaf(qz - p.z, w, gz);
    }
    float inv = 1.0f / aw;
    g_grad[cloud][qi] = make_float4(gx * inv, gy * inv, gz * inv, 0.f);
}

__global__ __launch_bounds__(T2)
void combine_kernel()
{
    __shared__ float sh[T2 / 32];
    const int tid = threadIdx.x;
    const int qi  = blockIdx.x * T2 + tid;

    float4 gT = g_grad[0][qi];
    float4 gS = g_grad[1][qi];

    float axT = gT.x + EPS_N, ayT = gT.y + EPS_N, azT = gT.z + EPS_N;
    float axS = gS.x + EPS_N, ayS = gS.y + EPS_N, azS = gS.z + EPS_N;
    float uT = sqrtf(fmaf(axT, axT, fmaf(ayT, ayT, azT * azT)));
    float uS = sqrtf(fmaf(axS, axS, fmaf(ayS, ayS, azS * azS)));

    float e1 = fabsf(uT - uS);
    float e2 = fabsf(gS.x - gT.x) + fabsf(gS.y - gT.y) + fabsf(gS.z - gT.z);
    float t  = e1 + e2;
    float v  = t * __expf(-BETA * t);

#pragma unroll
    for (int o = 16; o > 0; o >>= 1) v += __shfl_down_sync(0xFFFFFFFFu, v, o);
    if ((tid & 31) == 0) sh[tid >> 5] = v;
    __syncthreads();
    if (tid == 0) {
        float s = 0.f;
#pragma unroll
        for (int w = 0; w < T2 / 32; ++w) s += sh[w];
        g_partial[blockIdx.x] = s;
    }
}

__global__ void final_reduce(float* __restrict__ out)
{
    __shared__ float sh[4];
    int tid = threadIdx.x;   // 128 threads
    float v = (tid < NB2) ? g_partial[tid] : 0.f;
#pragma unroll
    for (int o = 16; o > 0; o >>= 1) v += __shfl_down_sync(0xFFFFFFFFu, v, o);
    if ((tid & 31) == 0) sh[tid >> 5] = v;
    __syncthreads();
    if (tid == 0) {
        float s = sh[0] + sh[1] + sh[2] + sh[3];
        out[0] = s * (1.0f / (float)QTOT);
    }
}

extern "C" void kernel_launch(void* const* d_in, const int* in_sizes, int n_in,
                              void* d_out, int out_size)
{
    const float* src   = (const float*)d_in[0];
    const float* tgt   = (const float*)d_in[1];
    const float* noise = (const float*)d_in[2];
    (void)in_sizes; (void)n_in; (void)out_size;

    dim3 grid1(GX1, 2, 1);
    knn_grad_kernel<<<grid1, T1>>>(src, tgt, noise);
    combine_kernel<<<NB2, T2>>>();
    final_reduce<<<1, 128>>>((float*)d_out);
}

// round 4
// speedup vs baseline: 3.3548x; 1.3513x over previous
#include <cuda_runtime.h>

#define NPTS    2048
#define UPR     10
#define NJIT    (NPTS*UPR)           // 20480 jittered queries
#define QTOT    (NJIT + NPTS)        // 22528 total queries
#define KNN     5
#define T1      256                  // kernel1 block size (128 pairs, SPLIT=2)
#define QPB1    (T1/2)               // 128 queries per block
#define GX1     (QTOT/QPB1)          // 176
#define T2      256
#define NB2     (QTOT/T2)            // 88
#define EPS_D   1e-8f
#define EPS_N   1e-10f
#define BETA    3.0f
#define STDV    0.05f
#define IDXMASK 0xFFFFF800u          // high 21 bits = d2, low 11 bits = index

// Per-(cloud, query) weighted udf gradient. [0]=tgt cloud, [1]=src cloud.
__device__ float4 g_grad[2][QTOT];
__device__ float  g_partial[NB2];

__device__ __forceinline__ void ins5key(int key, int& s0, int& s1, int& s2, int& s3, int& s4) {
    s4 = key;
    int a;
    a = min(s3, s4); s4 = max(s3, s4); s3 = a;
    a = min(s2, s3); s3 = max(s2, s3); s2 = a;
    a = min(s1, s2); s2 = max(s1, s2); s1 = a;
    a = min(s0, s1); s1 = max(s0, s1); s0 = a;
}

__global__ __launch_bounds__(T1)
void knn_grad_kernel(const float* __restrict__ src,
                     const float* __restrict__ tgt,
                     const float* __restrict__ noise)
{
    __shared__ float4 sC[NPTS];      // {x, y, z, |p|^2}  32 KB

    const int tid   = threadIdx.x;
    const int cloud = blockIdx.y;    // 0 = tgt, 1 = src
    const float* __restrict__ pts = cloud ? src : tgt;

    // Cooperative load of this block's cloud.
    for (int i = tid; i < NPTS; i += T1) {
        float x = pts[3*i], y = pts[3*i+1], z = pts[3*i+2];
        sC[i] = make_float4(x, y, z, fmaf(x, x, fmaf(y, y, z * z)));
    }
    __syncthreads();

    const int qi  = blockIdx.x * QPB1 + (tid >> 1);
    const int par = tid & 1;

    // Build this pair's query point.
    float qx, qy, qz;
    if (qi < NJIT) {
        int m = qi / UPR;
        qx = fmaf(noise[3*qi + 0], STDV, tgt[3*m + 0]);
        qy = fmaf(noise[3*qi + 1], STDV, tgt[3*m + 1]);
        qz = fmaf(noise[3*qi + 2], STDV, tgt[3*m + 2]);
    } else {
        int m = qi - NJIT;
        qx = src[3*m + 0];
        qy = src[3*m + 1];
        qz = src[3*m + 2];
    }
    const float qx2 = -2.0f * qx, qy2 = -2.0f * qy, qz2 = -2.0f * qz;
    const float q2  = fmaf(qx, qx, fmaf(qy, qy, qz * qz));

    // Top-5 packed keys (ascending in d2-space). Init huge.
    int s0 = 0x7F000000, s1 = 0x7F000001, s2 = 0x7F000002,
        s3 = 0x7F000003, s4 = 0x7F000004;
    float thR = __int_as_float(s4) - q2;   // threshold pre-translated to r-space

    // Scan this lane's half of the points (interleaved).
#pragma unroll 8
    for (int jj = 0; jj < NPTS / 2; ++jj) {
        int j = (jj << 1) + par;
        float4 p = sC[j];
        float r  = fmaf(p.x, qx2, fmaf(p.y, qy2, fmaf(p.z, qz2, p.w)));
        if (r < thR) {
            float d2 = fmaxf(r + q2, 0.0f);
            int key = (int)((__float_as_uint(d2) & IDXMASK) | (unsigned)j);
            ins5key(key, s0, s1, s2, s3, s4);
            thR = __int_as_float(s4) - q2;
        }
    }

    // Merge partner lane's top-5 (disjoint index sets -> union top-5).
    {
        int o0 = __shfl_xor_sync(0xFFFFFFFFu, s0, 1);
        int o1 = __shfl_xor_sync(0xFFFFFFFFu, s1, 1);
        int o2 = __shfl_xor_sync(0xFFFFFFFFu, s2, 1);
        int o3 = __shfl_xor_sync(0xFFFFFFFFu, s3, 1);
        int o4 = __shfl_xor_sync(0xFFFFFFFFu, s4, 1);
        if (o0 < s4) ins5key(o0, s0, s1, s2, s3, s4);
        if (o1 < s4) ins5key(o1, s0, s1, s2, s3, s4);
        if (o2 < s4) ins5key(o2, s0, s1, s2, s3, s4);
        if (o3 < s4) ins5key(o3, s0, s1, s2, s3, s4);
        if (o4 < s4) ins5key(o4, s0, s1, s2, s3, s4);
    }

    // Leader lane: exact recompute for the 5 selected indices.
    if (par == 0) {
        float aw = 0.f, gx = 0.f, gy = 0.f, gz = 0.f;
        int keys[KNN] = {s0, s1, s2, s3, s4};
#pragma unroll
        for (int k = 0; k < KNN; ++k) {
            int idx = keys[k] & 2047;
            float4 p = sC[idx];
            float r  = fmaf(p.x, qx2, fmaf(p.y, qy2, fmaf(p.z, qz2, p.w)));
            float d2 = fmaxf(r + q2, 0.0f);
            float w  = 1.0f / (d2 + EPS_D);
            aw += w;
            gx = fmaf(qx - p.x, w, gx);
            gy = fmaf(qy - p.y, w, gy);
            gz = fmaf(qz - p.z, w, gz);
        }
        float inv = 1.0f / aw;
        g_grad[cloud][qi] = make_float4(gx * inv, gy * inv, gz * inv, 0.f);
    }
}

__global__ __launch_bounds__(T2)
void combine_kernel()
{
    __shared__ float sh[T2 / 32];
    const int tid = threadIdx.x;
    const int qi  = blockIdx.x * T2 + tid;

    float4 gT = g_grad[0][qi];
    float4 gS = g_grad[1][qi];

    float axT = gT.x + EPS_N, ayT = gT.y + EPS_N, azT = gT.z + EPS_N;
    float axS = gS.x + EPS_N, ayS = gS.y + EPS_N, azS = gS.z + EPS_N;
    float uT = sqrtf(fmaf(axT, axT, fmaf(ayT, ayT, azT * azT)));
    float uS = sqrtf(fmaf(axS, axS, fmaf(ayS, ayS, azS * azS)));

    float e1 = fabsf(uT - uS);
    float e2 = fabsf(gS.x - gT.x) + fabsf(gS.y - gT.y) + fabsf(gS.z - gT.z);
    float t  = e1 + e2;
    float v  = t * __expf(-BETA * t);

#pragma unroll
    for (int o = 16; o > 0; o >>= 1) v += __shfl_down_sync(0xFFFFFFFFu, v, o);
    if ((tid & 31) == 0) sh[tid >> 5] = v;
    __syncthreads();
    if (tid == 0) {
        float s = 0.f;
#pragma unroll
        for (int w = 0; w < T2 / 32; ++w) s += sh[w];
        g_partial[blockIdx.x] = s;
    }
}

__global__ void final_reduce(float* __restrict__ out)
{
    __shared__ float sh[4];
    int tid = threadIdx.x;   // 128 threads
    float v = (tid < NB2) ? g_partial[tid] : 0.f;
#pragma unroll
    for (int o = 16; o > 0; o >>= 1) v += __shfl_down_sync(0xFFFFFFFFu, v, o);
    if ((tid & 31) == 0) sh[tid >> 5] = v;
    __syncthreads();
    if (tid == 0) {
        float s = sh[0] + sh[1] + sh[2] + sh[3];
        out[0] = s * (1.0f / (float)QTOT);
    }
}

extern "C" void kernel_launch(void* const* d_in, const int* in_sizes, int n_in,
                              void* d_out, int out_size)
{
    const float* src   = (const float*)d_in[0];
    const float* tgt   = (const float*)d_in[1];
    const float* noise = (const float*)d_in[2];
    (void)in_sizes; (void)n_in; (void)out_size;

    dim3 grid1(GX1, 2, 1);
    knn_grad_kernel<<<grid1, T1>>>(src, tgt, noise);
    combine_kernel<<<NB2, T2>>>();
    final_reduce<<<1, 128>>>((float*)d_out);
}